// round 16
// baseline (speedup 1.0000x reference)
#include <cuda_runtime.h>
#include <cuda_bf16.h>
#include <cstdint>

// NEAT DAG — R14: warp-specialized overlap.
// x[4096,512] f32, W[1536,2048] f32 lower-tri, b[1536], out[4096,256].
// 128 CTAs x 32 batch rows, 512 threads:
//   warps 0-11: GEMM (3 groups x 4 warps, 16x32 tiles, 3-way split-K,
//               6 double-buffered SMEM buffers, bar.sync 1,480)
//   warps 12-14: diag/bias staging helpers
//   warp 15: register-resident 64-node triangle, OVERLAPPED with the next
//            chunk's independent panel blocks. Join via bar.sync 0,512 only
//            for the one dependent block per chunk.

#define NTH 512
#define BR 32
#define NIN 512
#define NN 2048
#define NCHUNK 24
#define ZST 66

__device__ __align__(256) __nv_bfloat16 g_Ahi[4096u * 2048u];
__device__ __align__(256) __nv_bfloat16 g_Alo[4096u * 2048u];
__device__ __align__(256) __nv_bfloat16 g_Whi[1536u * 2048u];
__device__ __align__(256) __nv_bfloat16 g_Wlo[1536u * 2048u];

// ---- smem layout (bytes) ----
#define OFF_BIAS 0
#define OFF_ZSM  256                   // 32*66*4 = 8448
#define OFF_WD   8704                  // 64*68*4 = 17408
#define OFF_BUFS 26624                 // 6 buffers (3 groups x 2 parity)
#define BUFSZ    24576                 // AHI 4K | ALO 4K | WHI 8K | WLO 8K
#define SMEM_SZ  (OFF_BUFS + 6 * BUFSZ)  // 174080
#define AHI 0
#define ALO 4096
#define WHI 8192
#define WLO 16384

#define SW128(b) ((b) ^ (((b) >> 3) & 0x70))
#define BAR_ALL() asm volatile("bar.sync 0, 512;" ::: "memory")
#define BAR_G()   asm volatile("bar.sync 1, 480;" ::: "memory")

__device__ __forceinline__ uint32_t smem_u32(const void* p) {
    uint32_t a;
    asm("{ .reg .u64 t; cvta.to.shared.u64 t, %1; cvt.u32.u64 %0, t; }" : "=r"(a) : "l"(p));
    return a;
}
__device__ __forceinline__ void ldm4(uint32_t* r, uint32_t addr) {
    asm volatile("ldmatrix.sync.aligned.m8n8.x4.shared.b16 {%0,%1,%2,%3}, [%4];"
                 : "=r"(r[0]), "=r"(r[1]), "=r"(r[2]), "=r"(r[3]) : "r"(addr));
}
__device__ __forceinline__ void mma_bf16(float* d, const uint32_t* a,
                                         uint32_t b0, uint32_t b1) {
    asm volatile(
        "mma.sync.aligned.m16n8k16.row.col.f32.bf16.bf16.f32 "
        "{%0,%1,%2,%3}, {%4,%5,%6,%7}, {%8,%9}, {%0,%1,%2,%3};"
        : "+f"(d[0]), "+f"(d[1]), "+f"(d[2]), "+f"(d[3])
        : "r"(a[0]), "r"(a[1]), "r"(a[2]), "r"(a[3]), "r"(b0), "r"(b1));
}
__device__ __forceinline__ void split4(float4 v, __nv_bfloat16* h, __nv_bfloat16* l) {
    float f[4] = {v.x, v.y, v.z, v.w};
    #pragma unroll
    for (int j = 0; j < 4; j++) {
        h[j] = __float2bfloat16(f[j]);
        l[j] = __float2bfloat16(f[j] - __bfloat162float(h[j]));
    }
}

#define XN4 (4096 * 512 / 4)
#define WN4 (1536 * 2048 / 4)
__global__ void conv_kernel(const float* __restrict__ x, const float* __restrict__ W) {
    int idx = blockIdx.x * blockDim.x + threadIdx.x;
    __align__(8) __nv_bfloat16 h[4], l[4];
    if (idx < XN4) {
        int r = idx >> 7, c = (idx & 127) * 4;
        split4(*(const float4*)&x[(size_t)r * NIN + c], h, l);
        size_t o = (size_t)r * NN + c;
        *(uint2*)&g_Ahi[o] = *(uint2*)h;
        *(uint2*)&g_Alo[o] = *(uint2*)l;
    } else if (idx < XN4 + WN4) {
        int j = idx - XN4;
        int r = j >> 9, c = (j & 511) * 4;
        size_t o = (size_t)r * NN + c;
        split4(*(const float4*)&W[o], h, l);
        *(uint2*)&g_Whi[o] = *(uint2*)h;
        *(uint2*)&g_Wlo[o] = *(uint2*)l;
    }
}

__global__ void __launch_bounds__(NTH, 1)
neat_mma_kernel(const float* __restrict__ W,
                const float* __restrict__ bias,
                float* __restrict__ out)
{
    extern __shared__ char sm[];
    const uint32_t sb = smem_u32(sm);
    const int tid = threadIdx.x;
    const int lane = tid & 31, wrp = tid >> 5;
    const int row0 = blockIdx.x * BR;

    float* biasS = (float*)(sm + OFF_BIAS);
    float* zSm   = (float*)(sm + OFF_ZSM);    // [32][66], bias included
    float* Wd    = (float*)(sm + OFF_WD);     // [64][68] fp32 diag

    // ======================= T path: warp 15 =======================
    if (wrp == 15) {
        for (int c = 0; c < NCHUNK; c++) {
            BAR_ALL();                         // handoff: zSm(c), Wd(c) ready
            const int g0 = NIN + 64 * c;
            const int row = lane;
            float z[64];
            #pragma unroll
            for (int j = 0; j < 64; j++) z[j] = zSm[row * ZST + j];
            #pragma unroll
            for (int j = 0; j < 64; j++) {
                float t5 = fminf(fmaxf(5.0f * z[j], -60.0f), 60.0f);
                float o  = __fdividef(1.0f, 1.0f + __expf(-t5));
                __nv_bfloat16 h = __float2bfloat16(o);
                size_t go = (size_t)(row0 + row) * NN + g0 + j;
                g_Ahi[go] = h;
                g_Alo[go] = __float2bfloat16(o - __bfloat162float(h));
                if (g0 + j >= NN - 256)
                    out[(size_t)(row0 + row) * 256 + (g0 + j - (NN - 256))] = o;
                #pragma unroll
                for (int k = j + 1; k < 64; k++)
                    z[k] = fmaf(Wd[k * 68 + j], o, z[k]);
            }
            __threadfence_block();
            BAR_ALL();                         // join: triangle(c) done
        }
        return;
    }

    // ======================= G path: warps 0-14 =======================
    const int grp = wrp >> 2, sub = wrp & 3;   // grp 0-2 compute (wrp<12)
    const int rt16 = (sub & 1) << 4;
    const int c0   = (sub >> 1) << 5;
    const int mrow = lane & 7, mid = lane >> 3;
    const int aRowB  = (rt16 + mrow + ((mid & 1) << 3)) * 128 + ((mid >> 1) << 4);
    const int wRowB0 = (c0 + mrow + ((mid >> 1) << 3)) * 128 + ((mid & 1) << 4);
    const int wRowB1 = wRowB0 + 16 * 128;

    // per-thread staging descriptors (tid < 384), 4 items per block
    const __nv_bfloat16* sArr[4];
    size_t   sOff[4];
    bool     sIsW[4];
    uint32_t sDst[4];
    if (tid < 384) {
        #pragma unroll
        for (int i = 0; i < 4; i++) {
            int r = tid + 384 * i;
            if (r < 512) {
                bool hi = r < 256; int rr = r & 255;
                int row = rr >> 3, sg = rr & 7;
                sArr[i] = hi ? g_Ahi : g_Alo;
                sOff[i] = (size_t)(row0 + row) * NN + 8 * sg;
                sIsW[i] = false;
                sDst[i] = (hi ? AHI : ALO) + SW128((uint32_t)(row * 128 + sg * 16));
            } else {
                int q = r - 512; bool hi = q < 512; if (!hi) q -= 512;
                int wr = q >> 3, sg = q & 7;
                sArr[i] = hi ? g_Whi : g_Wlo;
                sOff[i] = (size_t)wr * NN + 8 * sg;
                sIsW[i] = true;
                sDst[i] = (hi ? WHI : WLO) + SW128((uint32_t)(wr * 128 + sg * 16));
            }
        }
    }

    float d[4][4];

    // ---- helpers as lambdas ----
    auto zero_acc = [&]() {
        #pragma unroll
        for (int t = 0; t < 4; t++)
            #pragma unroll
            for (int e = 0; e < 4; e++) d[t][e] = 0.0f;
    };
    // direct stage of one block (kb) of chunk m into buffer g,par
    auto stage_block = [&](int m, int kb, int g, int par) {
        if (tid < 384) {
            char* bp = sm + OFF_BUFS + (g * 2 + par) * BUFSZ;
            size_t wadd = (size_t)(64 * m) * NN;
            #pragma unroll
            for (int i = 0; i < 4; i++) {
                const __nv_bfloat16* src = sArr[i] + sOff[i] + (sIsW[i] ? wadd : 0) + kb;
                *(uint4*)(bp + sDst[i]) = *(const uint4*)src;
            }
        }
    };
    auto compute_block = [&](uint32_t bufoff) {
        const uint32_t bb = sb + bufoff;
        #pragma unroll
        for (int ks = 0; ks < 4; ks++) {
            uint32_t koff = ks * 32;
            uint32_t ah[4], al[4], wh0[4], wh1[4], wl0[4], wl1[4];
            ldm4(ah,  bb + AHI + SW128((uint32_t)(aRowB  + koff)));
            ldm4(al,  bb + ALO + SW128((uint32_t)(aRowB  + koff)));
            ldm4(wh0, bb + WHI + SW128((uint32_t)(wRowB0 + koff)));
            ldm4(wh1, bb + WHI + SW128((uint32_t)(wRowB1 + koff)));
            ldm4(wl0, bb + WLO + SW128((uint32_t)(wRowB0 + koff)));
            ldm4(wl1, bb + WLO + SW128((uint32_t)(wRowB1 + koff)));
            mma_bf16(d[0], ah, wh0[0], wh0[1]);
            mma_bf16(d[0], ah, wl0[0], wl0[1]);
            mma_bf16(d[0], al, wh0[0], wh0[1]);
            mma_bf16(d[1], ah, wh0[2], wh0[3]);
            mma_bf16(d[1], ah, wl0[2], wl0[3]);
            mma_bf16(d[1], al, wh0[2], wh0[3]);
            mma_bf16(d[2], ah, wh1[0], wh1[1]);
            mma_bf16(d[2], ah, wl1[0], wl1[1]);
            mma_bf16(d[2], al, wh1[0], wh1[1]);
            mma_bf16(d[3], ah, wh1[2], wh1[3]);
            mma_bf16(d[3], ah, wl1[2], wl1[3]);
            mma_bf16(d[3], al, wh1[2], wh1[3]);
        }
    };
    // pipelined free-block loop for chunk m with F free blocks
    auto free_loop = [&](int m, int F) {
        int nit = (F + 2) / 3;
        stage_block(m, 0, 0, 0);
        if (1 < F) stage_block(m, 64, 1, 0);
        if (2 < F) stage_block(m, 128, 2, 0);
        BAR_G();
        size_t wadd = (size_t)(64 * m) * NN;
        for (int it = 0; it < nit; it++) {
            const int par = it & 1;
            const bool pre = (it + 1 < nit);
            uint4 pf[3][4];
            bool act[3];
            if (tid < 384 && pre) {
                #pragma unroll
                for (int g = 0; g < 3; g++) {
                    int b = 3 * (it + 1) + g;
                    act[g] = (b < F);
                    if (act[g]) {
                        int kb = 64 * b;
                        #pragma unroll
                        for (int i = 0; i < 4; i++) {
                            const __nv_bfloat16* src =
                                sArr[i] + sOff[i] + (sIsW[i] ? wadd : 0) + kb;
                            pf[g][i] = *(const uint4*)src;
                        }
                    }
                }
            }
            if (wrp < 12 && (3 * it + grp) < F)
                compute_block((uint32_t)(OFF_BUFS + (grp * 2 + par) * BUFSZ));
            if (tid < 384 && pre) {
                int npar = (it + 1) & 1;
                #pragma unroll
                for (int g = 0; g < 3; g++) {
                    if (act[g]) {
                        char* bp = sm + OFF_BUFS + (g * 2 + npar) * BUFSZ;
                        #pragma unroll
                        for (int i = 0; i < 4; i++)
                            *(uint4*)(bp + sDst[i]) = pf[g][i];
                    }
                }
            }
            BAR_G();
        }
    };
    auto stage_wd_bias = [&](int m) {
        if (wrp >= 12) {            // tid 384..479
            int h = tid - 384;      // 0..95
            if (h < 64) biasS[h] = bias[64 * m + h];
            for (int f = h; f < 1024; f += 96) {
                int row = f >> 4, q = f & 15;
                *(float4*)&Wd[row * 68 + 4 * q] =
                    *(const float4*)&W[(size_t)(64 * m + row) * NN + (NIN + 64 * m) + 4 * q];
            }
        }
    };
    auto merge = [&]() {
        int rw = rt16 + (lane >> 2);
        int cbb = 2 * (lane & 3);
        if (wrp < 4) {
            #pragma unroll
            for (int t = 0; t < 4; t++) {
                int cb = c0 + 8 * t + cbb;
                *(float2*)&zSm[rw * ZST + cb] =
                    make_float2(d[t][0] + biasS[cb], d[t][1] + biasS[cb + 1]);
                *(float2*)&zSm[(rw + 8) * ZST + cb] =
                    make_float2(d[t][2] + biasS[cb], d[t][3] + biasS[cb + 1]);
            }
        }
        BAR_G();
        if (wrp >= 4 && wrp < 8) {
            #pragma unroll
            for (int t = 0; t < 4; t++) {
                int cb = c0 + 8 * t + cbb;
                float2 a = *(float2*)&zSm[rw * ZST + cb];
                a.x += d[t][0]; a.y += d[t][1];
                *(float2*)&zSm[rw * ZST + cb] = a;
                a = *(float2*)&zSm[(rw + 8) * ZST + cb];
                a.x += d[t][2]; a.y += d[t][3];
                *(float2*)&zSm[(rw + 8) * ZST + cb] = a;
            }
        }
        BAR_G();
        if (wrp >= 8 && wrp < 12) {
            #pragma unroll
            for (int t = 0; t < 4; t++) {
                int cb = c0 + 8 * t + cbb;
                float2 a = *(float2*)&zSm[rw * ZST + cb];
                a.x += d[t][0]; a.y += d[t][1];
                *(float2*)&zSm[rw * ZST + cb] = a;
                a = *(float2*)&zSm[(rw + 8) * ZST + cb];
                a.x += d[t][2]; a.y += d[t][3];
                *(float2*)&zSm[(rw + 8) * ZST + cb] = a;
            }
        }
        BAR_G();
    };

    // ---- chunk 0 prologue (no dep block) ----
    zero_acc();
    free_loop(0, 8);
    stage_wd_bias(0);
    BAR_G();
    merge();

    // ---- main pipeline ----
    for (int c = 0; c < NCHUNK; c++) {
        BAR_ALL();                              // handoff c -> triangle(c) starts
        if (c < NCHUNK - 1) {
            int m = c + 1;
            zero_acc();
            free_loop(m, 7 + m);
        }
        BAR_ALL();                              // join: triangle(c) done
        if (c < NCHUNK - 1) {
            int m = c + 1;
            int kb_dep = 64 * (7 + m);          // = g0_m - 64
            stage_block(m, kb_dep, 0, 0);
            stage_wd_bias(m);
            BAR_G();
            if (wrp < 4) compute_block((uint32_t)(OFF_BUFS + 0));
            BAR_G();
            merge();
        }
    }
}

extern "C" void kernel_launch(void* const* d_in, const int* in_sizes, int n_in,
                              void* d_out, int out_size) {
    const float* x    = (const float*)d_in[0];
    const float* W    = (const float*)d_in[1];
    const float* bias = (const float*)d_in[2];
    float* out        = (float*)d_out;
    (void)in_sizes; (void)n_in; (void)out_size;

    conv_kernel<<<(XN4 + WN4 + NTH - 1) / NTH, NTH>>>(x, W);
    cudaFuncSetAttribute(neat_mma_kernel,
                         cudaFuncAttributeMaxDynamicSharedMemorySize, SMEM_SZ);
    neat_mma_kernel<<<4096 / BR, NTH, SMEM_SZ>>>(W, bias, out);
}